// round 7
// baseline (speedup 1.0000x reference)
#include <cuda_runtime.h>
#include <cuda_fp16.h>
#include <math.h>

constexpr int Bq   = 4;
constexpr int Nq   = 64;
constexpr int Fq   = 64;
constexpr int FINq = 32;
constexpr int EDIMq= 32;
constexpr int FFq  = Fq * Fq;          // 4096
constexpr int ROWS = Bq * Nq;          // 256 target rows (b,n)

__device__ float  g_H[ROWS * Fq];
__device__ int    g_cnt[ROWS];
__device__ int    g_midx[ROWS * Nq];
// Interleaved layout: per active slot, 2048 half2; entry [c] (c = ii*64+j, ii<32)
// holds ( A[ii][j], A[ii+32][j] ).
__device__ __align__(16) __half2 g_Amat[(size_t)ROWS * Nq * (FFq / 2)];

__device__ __forceinline__ float sigm(float x) { return 1.0f / (1.0f + expf(-x)); }

__device__ __forceinline__ unsigned long long pack2(float lo, float hi) {
    unsigned long long r;
    asm("mov.b64 %0, {%1, %2};" : "=l"(r) : "f"(lo), "f"(hi));
    return r;
}
__device__ __forceinline__ void unpack2(unsigned long long v, float& lo, float& hi) {
    asm("mov.b64 {%0, %1}, %2;" : "=f"(lo), "=f"(hi) : "l"(v));
}
__device__ __forceinline__ unsigned long long ffma2(
    unsigned long long a, unsigned long long b, unsigned long long c) {
    unsigned long long d;
    asm("fma.rn.f32x2 %0, %1, %2, %3;" : "=l"(d) : "l"(a), "l"(b), "l"(c));
    return d;
}
__device__ __forceinline__ __half2 h2(unsigned int u) {
    return *reinterpret_cast<__half2*>(&u);
}

// ---------------------------------------------------------------------------
// Kernel 1: H0 = relu(X@W_embed + b) + parallel ballot mask compaction
// ---------------------------------------------------------------------------
__global__ __launch_bounds__(64) void k_embed(
    const float* __restrict__ X, const float* __restrict__ A,
    const float* __restrict__ W_embed, const float* __restrict__ b_embed,
    float* __restrict__ Hout)
{
    int row = blockIdx.x;
    int t = threadIdx.x;
    __shared__ float xs[FINq];
    if (t < FINq) xs[t] = X[row * FINq + t];
    __syncthreads();

    float acc = b_embed[t];
#pragma unroll
    for (int k = 0; k < FINq; k++) acc += xs[k] * W_embed[k * Fq + t];
    Hout[row * Fq + t] = fmaxf(acc, 0.0f);

    if (t < 32) {
        const float* Arow = A + (size_t)row * Nq;
        unsigned a0 = (Arow[t] > 0.5f) ? 1u : 0u;
        unsigned a1 = (Arow[32 + t] > 0.5f) ? 1u : 0u;
        unsigned m0 = __ballot_sync(0xffffffffu, a0);
        unsigned m1 = __ballot_sync(0xffffffffu, a1);
        unsigned lanemask = (t == 0) ? 0u : (0xffffffffu >> (32 - t));
        int n0 = __popc(m0);
        if (a0) g_midx[row * Nq + __popc(m0 & lanemask)] = t;
        if (a1) g_midx[row * Nq + n0 + __popc(m1 & lanemask)] = 32 + t;
        if (t == 0) g_cnt[row] = n0 + __popc(m1);
    }
}

// ---------------------------------------------------------------------------
// Kernel 2: edge matrices for ACTIVE edges, packed f32x2 FMA.
// Thread t computes feature-pair columns (c, c+2048) -> interleaved half2 out.
// Block: 2 target rows x 256 c-values. grid = (128, 8).
// ---------------------------------------------------------------------------
__global__ __launch_bounds__(256) void k_edge(
    const float* __restrict__ E, const float* __restrict__ W_edge,
    const float* __restrict__ b_edge)
{
    int rp = blockIdx.x;
    int c0 = blockIdx.y * 256;
    int t  = threadIdx.x;

    __shared__ unsigned long long Es2[2 * Nq][EDIMq];
    __shared__ int   s_slot[2 * Nq];
    __shared__ int   s_ne;

    if (t == 0) {
        int ne = 0;
        for (int r = 0; r < 2; r++) {
            int row = rp * 2 + r;
            int cnt = g_cnt[row];
            for (int k = 0; k < cnt; k++) s_slot[ne++] = row * Nq + k;
        }
        s_ne = ne;
    }
    __syncthreads();
    int ne = s_ne;

    for (int i = t; i < ne * EDIMq; i += 256) {
        int kk = i >> 5, e = i & 31;
        int slot = s_slot[kk];
        int row  = slot >> 6;
        int m    = g_midx[slot];
        float v  = E[((size_t)row * Nq + m) * EDIMq + e];
        Es2[kk][e] = pack2(v, v);
    }
    __syncthreads();

    int c_a = c0 + t;            // ii*64+j, ii<32
    int c_b = c_a + 2048;        // (ii+32)*64+j
    unsigned long long w01[EDIMq];
#pragma unroll
    for (int e = 0; e < EDIMq; e++)
        w01[e] = pack2(W_edge[(size_t)e * FFq + c_a], W_edge[(size_t)e * FFq + c_b]);
    unsigned long long bias01 = pack2(b_edge[c_a], b_edge[c_b]);

    int kk = 0;
    for (; kk + 2 <= ne; kk += 2) {
        unsigned long long acc0 = bias01, acc1 = bias01;
#pragma unroll
        for (int e = 0; e < EDIMq; e++) {
            acc0 = ffma2(Es2[kk][e],     w01[e], acc0);
            acc1 = ffma2(Es2[kk + 1][e], w01[e], acc1);
        }
        float a0, a1, b0v, b1v;
        unpack2(acc0, a0, a1);
        unpack2(acc1, b0v, b1v);
        g_Amat[(size_t)s_slot[kk]     * (FFq / 2) + c_a] =
            __floats2half2_rn(fmaxf(a0, 0.0f), fmaxf(a1, 0.0f));
        g_Amat[(size_t)s_slot[kk + 1] * (FFq / 2) + c_a] =
            __floats2half2_rn(fmaxf(b0v, 0.0f), fmaxf(b1v, 0.0f));
    }
    if (kk < ne) {
        unsigned long long acc0 = bias01;
#pragma unroll
        for (int e = 0; e < EDIMq; e++)
            acc0 = ffma2(Es2[kk][e], w01[e], acc0);
        float a0, a1;
        unpack2(acc0, a0, a1);
        g_Amat[(size_t)s_slot[kk] * (FFq / 2) + c_a] =
            __floats2half2_rn(fmaxf(a0, 0.0f), fmaxf(a1, 0.0f));
    }
}

// ---------------------------------------------------------------------------
// Kernel 3: one round. 512 threads/row: ee = edge parity, ii = feature (0..31,
// pairs with ii+32), jq = j-chunk of 8. Per edge per thread: 2 LDG.128 of
// interleaved half2 + 2 LDS.128 of duplicated h + 8 HFMA2. 8-edge clamped
// unroll -> 16 LDG.128 in flight per thread. fp32 accumulation across edges.
// ---------------------------------------------------------------------------
__global__ __launch_bounds__(512) void k_round(
    const float* __restrict__ Hin, float* __restrict__ Hout,
    const float* __restrict__ gk, const float* __restrict__ grk,
    const float* __restrict__ gb, const float* __restrict__ grb)
{
    int row = blockIdx.x;
    int b = row >> 6;
    int t = threadIdx.x;
    int ee = t >> 8;              // 0/1: edge parity
    int tt = t & 255;
    int ii = tt >> 3, jq = tt & 7;

    __shared__ __half2 hs2[Nq + 1][Fq];   // duplicated-h half2, row Nq = zeros (16.25KB)
    __shared__ float xold[Fq], aggv[Fq], h1[Fq];
    __shared__ float aggp[2][Fq];
    __shared__ float xg1[3 * Fq], xg2[3 * Fq], hg2[3 * Fq];

    int cnt = g_cnt[row];

    // stage sources as duplicated half2; zero pad row
    for (int idx = t; idx < cnt * Fq; idx += 512) {
        int e = idx >> 6, j = idx & 63;
        int m = g_midx[row * Nq + e];
        float v = Hin[((size_t)b * Nq + m) * Fq + j];
        hs2[e][j] = __float2half2_rn(v);
    }
    if (t < Fq) hs2[Nq][t] = __float2half2_rn(0.0f);
    if (t >= 64 && t < 128) xold[t - 64] = Hin[(size_t)row * Fq + (t - 64)];
    __syncthreads();

    // edges for this parity: e = ee, ee+2, ...
    int net = (cnt > ee) ? ((cnt - ee + 1) >> 1) : 0;
    const uint4* Abase = reinterpret_cast<const uint4*>(g_Amat)
                       + (size_t)row * Nq * 512 + ii * 16 + jq * 2;
    float flo = 0.0f, fhi = 0.0f;

    for (int k0 = 0; k0 < net; k0 += 8) {
#pragma unroll
        for (int u = 0; u < 8; u++) {
            int k = k0 + u;
            bool valid = (k < net);
            int e = valid ? (ee + 2 * k) : 0;          // clamp: finite data
            const uint4* ap = Abase + (size_t)e * 512;
            uint4 a0 = ap[0];
            uint4 a1 = ap[1];
            int hrow = valid ? e : Nq;                  // zeros when padded
            const uint4* hp = reinterpret_cast<const uint4*>(&hs2[hrow][jq * 8]);
            uint4 hA = hp[0];
            uint4 hB = hp[1];
            __half2 cA = __hmul2(h2(a0.x), h2(hA.x));
            cA = __hfma2(h2(a0.y), h2(hA.y), cA);
            cA = __hfma2(h2(a0.z), h2(hA.z), cA);
            cA = __hfma2(h2(a0.w), h2(hA.w), cA);
            __half2 cB = __hmul2(h2(a1.x), h2(hB.x));
            cB = __hfma2(h2(a1.y), h2(hB.y), cB);
            cB = __hfma2(h2(a1.z), h2(hB.z), cB);
            cB = __hfma2(h2(a1.w), h2(hB.w), cB);
            float2 f = __half22float2(__hadd2(cA, cB));
            flo += f.x;
            fhi += f.y;
        }
    }

    // reduce over jq (lane bits 0..2)
    flo += __shfl_xor_sync(0xffffffffu, flo, 1);
    flo += __shfl_xor_sync(0xffffffffu, flo, 2);
    flo += __shfl_xor_sync(0xffffffffu, flo, 4);
    fhi += __shfl_xor_sync(0xffffffffu, fhi, 1);
    fhi += __shfl_xor_sync(0xffffffffu, fhi, 2);
    fhi += __shfl_xor_sync(0xffffffffu, fhi, 4);
    if (jq == 0) {
        aggp[ee][ii] = flo;
        aggp[ee][ii + 32] = fhi;
    }
    __syncthreads();
    if (t < Fq) aggv[t] = aggp[0][t] + aggp[1][t];
    __syncthreads();

    // ---- GRU: one pass over gk computes both steps' input gates ----
    if (t < 192) {
        float a1 = gb[t], a2 = gb[t];
#pragma unroll 8
        for (int j = 0; j < Fq; j++) {
            float w = gk[j * 192 + t];
            a1 += xold[j] * w;
            a2 += aggv[j] * w;
        }
        xg1[t] = a1;
        xg2[t] = a2;
    }
    __syncthreads();
    if (t < Fq) {
        float z = sigm(xg1[t] + grb[t]);
        float rr = sigm(xg1[Fq + t] + grb[Fq + t]);
        float cand = tanhf(xg1[2 * Fq + t] + rr * grb[2 * Fq + t]);
        h1[t] = (1.0f - z) * cand;
    }
    __syncthreads();
    if (t < 192) {
        float hh = grb[t];
#pragma unroll 8
        for (int j = 0; j < Fq; j++) hh += h1[j] * grk[j * 192 + t];
        hg2[t] = hh;
    }
    __syncthreads();
    if (t < Fq) {
        float z = sigm(xg2[t] + hg2[t]);
        float rr = sigm(xg2[Fq + t] + hg2[Fq + t]);
        float cand = tanhf(xg2[2 * Fq + t] + rr * hg2[2 * Fq + t]);
        Hout[(size_t)row * Fq + t] = z * h1[t] + (1.0f - z) * cand;
    }
}

// ---------------------------------------------------------------------------
extern "C" void kernel_launch(void* const* d_in, const int* in_sizes, int n_in,
                              void* d_out, int out_size)
{
    const float* X       = (const float*)d_in[0];
    const float* A       = (const float*)d_in[1];
    const float* E       = (const float*)d_in[2];
    const float* W_embed = (const float*)d_in[3];
    const float* b_embed = (const float*)d_in[4];
    const float* W_edge  = (const float*)d_in[5];
    const float* b_edge  = (const float*)d_in[6];
    const float* gk      = (const float*)d_in[7];
    const float* grk     = (const float*)d_in[8];
    const float* gb      = (const float*)d_in[9];
    const float* grb     = (const float*)d_in[10];
    float* out = (float*)d_out;

    float* hbuf = nullptr;
    cudaGetSymbolAddress((void**)&hbuf, g_H);

    k_embed<<<ROWS, 64>>>(X, A, W_embed, b_embed, hbuf);
    k_edge<<<dim3(ROWS / 2, 8), 256>>>(E, W_edge, b_edge);
    k_round<<<ROWS, 512>>>(hbuf, out,  gk, grk, gb, grb);
    k_round<<<ROWS, 512>>>(out,  hbuf, gk, grk, gb, grb);
    k_round<<<ROWS, 512>>>(hbuf, out,  gk, grk, gb, grb);
}

// round 8
// speedup vs baseline: 1.0361x; 1.0361x over previous
#include <cuda_runtime.h>
#include <cuda_fp16.h>
#include <math.h>

constexpr int Bq   = 4;
constexpr int Nq   = 64;
constexpr int Fq   = 64;
constexpr int FINq = 32;
constexpr int EDIMq= 32;
constexpr int FFq  = Fq * Fq;          // 4096
constexpr int ROWS = Bq * Nq;          // 256 target rows (b,n)

constexpr int NSTAGE = 4;              // cp.async pipeline stages
constexpr int CHUNK_BYTES = 16384;     // 2 edges * 8KB

__device__ float  g_H[ROWS * Fq];
__device__ int    g_cnt[ROWS];
__device__ int    g_midx[ROWS * Nq];
// Interleaved layout: per active slot, 2048 half2; entry [c] (c = ii*64+j, ii<32)
// holds ( A[ii][j], A[ii+32][j] ). Inactive slots stay zero (BSS zero-init,
// never written) -> padded edge reads contribute exactly 0.
__device__ __align__(16) __half2 g_Amat[(size_t)ROWS * Nq * (FFq / 2)];

__device__ __forceinline__ float sigm(float x) { return 1.0f / (1.0f + expf(-x)); }

__device__ __forceinline__ unsigned long long pack2(float lo, float hi) {
    unsigned long long r;
    asm("mov.b64 %0, {%1, %2};" : "=l"(r) : "f"(lo), "f"(hi));
    return r;
}
__device__ __forceinline__ void unpack2(unsigned long long v, float& lo, float& hi) {
    asm("mov.b64 {%0, %1}, %2;" : "=f"(lo), "=f"(hi) : "l"(v));
}
__device__ __forceinline__ unsigned long long ffma2(
    unsigned long long a, unsigned long long b, unsigned long long c) {
    unsigned long long d;
    asm("fma.rn.f32x2 %0, %1, %2, %3;" : "=l"(d) : "l"(a), "l"(b), "l"(c));
    return d;
}
__device__ __forceinline__ __half2 h2(unsigned int u) {
    return *reinterpret_cast<__half2*>(&u);
}
__device__ __forceinline__ void cp_async16(void* smem_ptr, const void* gptr) {
    unsigned sa = (unsigned)__cvta_generic_to_shared(smem_ptr);
    asm volatile("cp.async.cg.shared.global [%0], [%1], 16;" :: "r"(sa), "l"(gptr));
}
__device__ __forceinline__ void cp_commit() {
    asm volatile("cp.async.commit_group;");
}
template<int N> __device__ __forceinline__ void cp_wait() {
    asm volatile("cp.async.wait_group %0;" :: "n"(N));
}

// ---------------------------------------------------------------------------
// Kernel 1: H0 = relu(X@W_embed + b) + parallel ballot mask compaction
// ---------------------------------------------------------------------------
__global__ __launch_bounds__(64) void k_embed(
    const float* __restrict__ X, const float* __restrict__ A,
    const float* __restrict__ W_embed, const float* __restrict__ b_embed,
    float* __restrict__ Hout)
{
    int row = blockIdx.x;
    int t = threadIdx.x;
    __shared__ float xs[FINq];
    if (t < FINq) xs[t] = X[row * FINq + t];
    __syncthreads();

    float acc = b_embed[t];
#pragma unroll
    for (int k = 0; k < FINq; k++) acc += xs[k] * W_embed[k * Fq + t];
    Hout[row * Fq + t] = fmaxf(acc, 0.0f);

    if (t < 32) {
        const float* Arow = A + (size_t)row * Nq;
        unsigned a0 = (Arow[t] > 0.5f) ? 1u : 0u;
        unsigned a1 = (Arow[32 + t] > 0.5f) ? 1u : 0u;
        unsigned m0 = __ballot_sync(0xffffffffu, a0);
        unsigned m1 = __ballot_sync(0xffffffffu, a1);
        unsigned lanemask = (t == 0) ? 0u : (0xffffffffu >> (32 - t));
        int n0 = __popc(m0);
        if (a0) g_midx[row * Nq + __popc(m0 & lanemask)] = t;
        if (a1) g_midx[row * Nq + n0 + __popc(m1 & lanemask)] = 32 + t;
        if (t == 0) g_cnt[row] = n0 + __popc(m1);
    }
}

// ---------------------------------------------------------------------------
// Kernel 2: edge matrices for ACTIVE edges, packed f32x2 FMA, interleaved out.
// ---------------------------------------------------------------------------
__global__ __launch_bounds__(256) void k_edge(
    const float* __restrict__ E, const float* __restrict__ W_edge,
    const float* __restrict__ b_edge)
{
    int rp = blockIdx.x;
    int c0 = blockIdx.y * 256;
    int t  = threadIdx.x;

    __shared__ unsigned long long Es2[2 * Nq][EDIMq];
    __shared__ int   s_slot[2 * Nq];
    __shared__ int   s_ne;

    if (t == 0) {
        int ne = 0;
        for (int r = 0; r < 2; r++) {
            int row = rp * 2 + r;
            int cnt = g_cnt[row];
            for (int k = 0; k < cnt; k++) s_slot[ne++] = row * Nq + k;
        }
        s_ne = ne;
    }
    __syncthreads();
    int ne = s_ne;

    for (int i = t; i < ne * EDIMq; i += 256) {
        int kk = i >> 5, e = i & 31;
        int slot = s_slot[kk];
        int row  = slot >> 6;
        int m    = g_midx[slot];
        float v  = E[((size_t)row * Nq + m) * EDIMq + e];
        Es2[kk][e] = pack2(v, v);
    }
    __syncthreads();

    int c_a = c0 + t;            // ii*64+j, ii<32
    int c_b = c_a + 2048;        // (ii+32)*64+j
    unsigned long long w01[EDIMq];
#pragma unroll
    for (int e = 0; e < EDIMq; e++)
        w01[e] = pack2(W_edge[(size_t)e * FFq + c_a], W_edge[(size_t)e * FFq + c_b]);
    unsigned long long bias01 = pack2(b_edge[c_a], b_edge[c_b]);

    int kk = 0;
    for (; kk + 2 <= ne; kk += 2) {
        unsigned long long acc0 = bias01, acc1 = bias01;
#pragma unroll
        for (int e = 0; e < EDIMq; e++) {
            acc0 = ffma2(Es2[kk][e],     w01[e], acc0);
            acc1 = ffma2(Es2[kk + 1][e], w01[e], acc1);
        }
        float a0, a1, b0v, b1v;
        unpack2(acc0, a0, a1);
        unpack2(acc1, b0v, b1v);
        g_Amat[(size_t)s_slot[kk]     * (FFq / 2) + c_a] =
            __floats2half2_rn(fmaxf(a0, 0.0f), fmaxf(a1, 0.0f));
        g_Amat[(size_t)s_slot[kk + 1] * (FFq / 2) + c_a] =
            __floats2half2_rn(fmaxf(b0v, 0.0f), fmaxf(b1v, 0.0f));
    }
    if (kk < ne) {
        unsigned long long acc0 = bias01;
#pragma unroll
        for (int e = 0; e < EDIMq; e++)
            acc0 = ffma2(Es2[kk][e], w01[e], acc0);
        float a0, a1;
        unpack2(acc0, a0, a1);
        g_Amat[(size_t)s_slot[kk] * (FFq / 2) + c_a] =
            __floats2half2_rn(fmaxf(a0, 0.0f), fmaxf(a1, 0.0f));
    }
}

// ---------------------------------------------------------------------------
// Kernel 3: one round with cp.async 4-stage pipeline over 2-edge (16KB) chunks.
// 512 threads: ee = edge-in-chunk, ii = feature pair (0..31), jq = j-chunk.
// Loads bypass registers -> up to 48KB in flight per block.
// Dynamic smem layout:
//   [0, 64K)        : 4-stage Amat ring
//   [64K, +16.25K)  : hs2 (Nq+1 rows of 64 half2, duplicated-h)
//   then floats     : xold, aggv, h1, aggp[2], xg1, xg2, hg2
// ---------------------------------------------------------------------------
constexpr int SMEM_STAGE = NSTAGE * CHUNK_BYTES;                  // 65536
constexpr int SMEM_HS    = (Nq + 1) * Fq * 4;                     // 16640
constexpr int SMEM_FLT   = (64 * 3 + 128 + 192 * 3) * 4;          // 3584
constexpr int SMEM_TOTAL = SMEM_STAGE + SMEM_HS + SMEM_FLT;       // 85760

__global__ __launch_bounds__(512) void k_round(
    const float* __restrict__ Hin, float* __restrict__ Hout,
    const float* __restrict__ gk, const float* __restrict__ grk,
    const float* __restrict__ gb, const float* __restrict__ grb)
{
    extern __shared__ __align__(16) char smem[];
    char* stage = smem;
    __half2 (*hs2)[Fq] = reinterpret_cast<__half2(*)[Fq]>(smem + SMEM_STAGE);
    float* fl   = reinterpret_cast<float*>(smem + SMEM_STAGE + SMEM_HS);
    float* xold = fl;            // 64
    float* aggv = fl + 64;       // 64
    float* h1   = fl + 128;      // 64
    float* aggp = fl + 192;      // 2*64
    float* xg1  = fl + 320;      // 192
    float* xg2  = fl + 512;      // 192
    float* hg2  = fl + 704;      // 192

    int row = blockIdx.x;
    int b = row >> 6;
    int t = threadIdx.x;
    int ee = t >> 8;              // edge within chunk
    int tt = t & 255;
    int ii = tt >> 3, jq = tt & 7;

    int cnt = g_cnt[row];
    int nchunk = (cnt + 1) >> 1;

    const char* Asrc = reinterpret_cast<const char*>(g_Amat)
                     + (size_t)row * Nq * 8192;

    auto issue = [&](int c) {
        const char* src = Asrc + (size_t)c * CHUNK_BYTES;
        char* dst = stage + (c & (NSTAGE - 1)) * CHUNK_BYTES;
        cp_async16(dst + t * 16, src + t * 16);
        cp_async16(dst + t * 16 + 8192, src + t * 16 + 8192);
    };

    // prologue: fill NSTAGE-1 stages (empty commits keep group numbering)
#pragma unroll
    for (int s = 0; s < NSTAGE - 1; s++) {
        if (s < nchunk) issue(s);
        cp_commit();
    }

    // stage sources as duplicated half2 while copies are in flight
    for (int idx = t; idx < cnt * Fq; idx += 512) {
        int e = idx >> 6, j = idx & 63;
        int m = g_midx[row * Nq + e];
        float v = Hin[((size_t)b * Nq + m) * Fq + j];
        hs2[e][j] = __float2half2_rn(v);
    }
    if (t < Fq) hs2[cnt][t] = __float2half2_rn(0.0f);   // pad row for odd cnt
    if (t >= 64 && t < 128) xold[t - 64] = Hin[(size_t)row * Fq + (t - 64)];

    float flo = 0.0f, fhi = 0.0f;

    for (int c = 0; c < nchunk; c++) {
        cp_wait<NSTAGE - 2>();
        __syncthreads();          // chunk c visible to all; prev compute done

        const uint4* ap = reinterpret_cast<const uint4*>(
            stage + (c & (NSTAGE - 1)) * CHUNK_BYTES) + ee * 512 + ii * 16 + jq * 2;
        uint4 a0 = ap[0];
        uint4 a1 = ap[1];
        int e = 2 * c + ee;       // may be pad edge: A zeros, hs2 zeros
        const uint4* hp = reinterpret_cast<const uint4*>(&hs2[e][jq * 8]);
        uint4 hA = hp[0];
        uint4 hB = hp[1];
        __half2 cA = __hmul2(h2(a0.x), h2(hA.x));
        cA = __hfma2(h2(a0.y), h2(hA.y), cA);
        cA = __hfma2(h2(a0.z), h2(hA.z), cA);
        cA = __hfma2(h2(a0.w), h2(hA.w), cA);
        __half2 cB = __hmul2(h2(a1.x), h2(hB.x));
        cB = __hfma2(h2(a1.y), h2(hB.y), cB);
        cB = __hfma2(h2(a1.z), h2(hB.z), cB);
        cB = __hfma2(h2(a1.w), h2(hB.w), cB);
        float2 f = __half22float2(__hadd2(cA, cB));
        flo += f.x;
        fhi += f.y;

        int nx = c + NSTAGE - 1;
        if (nx < nchunk) issue(nx);
        cp_commit();
    }
    cp_wait<0>();

    // reduce over jq (lane bits 0..2)
    flo += __shfl_xor_sync(0xffffffffu, flo, 1);
    flo += __shfl_xor_sync(0xffffffffu, flo, 2);
    flo += __shfl_xor_sync(0xffffffffu, flo, 4);
    fhi += __shfl_xor_sync(0xffffffffu, fhi, 1);
    fhi += __shfl_xor_sync(0xffffffffu, fhi, 2);
    fhi += __shfl_xor_sync(0xffffffffu, fhi, 4);
    if (jq == 0) {
        aggp[ee * 64 + ii] = flo;
        aggp[ee * 64 + ii + 32] = fhi;
    }
    __syncthreads();
    if (t < Fq) aggv[t] = aggp[t] + aggp[64 + t];
    __syncthreads();

    // ---- GRU: one pass over gk computes both steps' input gates ----
    if (t < 192) {
        float a1 = gb[t], a2 = gb[t];
#pragma unroll 8
        for (int j = 0; j < Fq; j++) {
            float w = gk[j * 192 + t];
            a1 += xold[j] * w;
            a2 += aggv[j] * w;
        }
        xg1[t] = a1;
        xg2[t] = a2;
    }
    __syncthreads();
    if (t < Fq) {
        float z = sigm(xg1[t] + grb[t]);
        float rr = sigm(xg1[Fq + t] + grb[Fq + t]);
        float cand = tanhf(xg1[2 * Fq + t] + rr * grb[2 * Fq + t]);
        h1[t] = (1.0f - z) * cand;
    }
    __syncthreads();
    if (t < 192) {
        float hh = grb[t];
#pragma unroll 8
        for (int j = 0; j < Fq; j++) hh += h1[j] * grk[j * 192 + t];
        hg2[t] = hh;
    }
    __syncthreads();
    if (t < Fq) {
        float z = sigm(xg2[t] + hg2[t]);
        float rr = sigm(xg2[Fq + t] + hg2[Fq + t]);
        float cand = tanhf(xg2[2 * Fq + t] + rr * hg2[2 * Fq + t]);
        Hout[(size_t)row * Fq + t] = z * h1[t] + (1.0f - z) * cand;
    }
}

// ---------------------------------------------------------------------------
extern "C" void kernel_launch(void* const* d_in, const int* in_sizes, int n_in,
                              void* d_out, int out_size)
{
    const float* X       = (const float*)d_in[0];
    const float* A       = (const float*)d_in[1];
    const float* E       = (const float*)d_in[2];
    const float* W_embed = (const float*)d_in[3];
    const float* b_embed = (const float*)d_in[4];
    const float* W_edge  = (const float*)d_in[5];
    const float* b_edge  = (const float*)d_in[6];
    const float* gk      = (const float*)d_in[7];
    const float* grk     = (const float*)d_in[8];
    const float* gb      = (const float*)d_in[9];
    const float* grb     = (const float*)d_in[10];
    float* out = (float*)d_out;

    float* hbuf = nullptr;
    cudaGetSymbolAddress((void**)&hbuf, g_H);

    static bool attr_set = false;
    if (!attr_set) {
        cudaFuncSetAttribute(k_round, cudaFuncAttributeMaxDynamicSharedMemorySize,
                             SMEM_TOTAL);
        attr_set = true;
    }

    k_embed<<<ROWS, 64>>>(X, A, W_embed, b_embed, hbuf);
    k_edge<<<dim3(ROWS / 2, 8), 256>>>(E, W_edge, b_edge);
    k_round<<<ROWS, 512, SMEM_TOTAL>>>(hbuf, out,  gk, grk, gb, grb);
    k_round<<<ROWS, 512, SMEM_TOTAL>>>(out,  hbuf, gk, grk, gb, grb);
    k_round<<<ROWS, 512, SMEM_TOTAL>>>(hbuf, out,  gk, grk, gb, grb);
}